// round 3
// baseline (speedup 1.0000x reference)
#include <cuda_runtime.h>
#include <math.h>

#define DIM 4096
#define BSZ 1024
#define NW  12

#define BM 128
#define BN 64
#define BK 8
#define NT (DIM / BK)

typedef unsigned long long u64;

// ---- packed fp32x2 helpers (Blackwell-only; ptxas never auto-fuses these) ----
__device__ __forceinline__ u64 pack2(float lo, float hi) {
    u64 r; asm("mov.b64 %0, {%1, %2};" : "=l"(r) : "f"(lo), "f"(hi)); return r;
}
__device__ __forceinline__ u64 dup2(float v) { return pack2(v, v); }
__device__ __forceinline__ void unpack2(u64 v, float& lo, float& hi) {
    asm("mov.b64 {%0, %1}, %2;" : "=f"(lo), "=f"(hi) : "l"(v));
}
__device__ __forceinline__ void ffma2(u64& c, u64 a, u64 b) {
    asm("fma.rn.f32x2 %0, %1, %2, %0;" : "+l"(c) : "l"(a), "l"(b));
}

// Scratch (allocation-free rule: device globals)
__device__ float g_s2_re[DIM * BSZ];   // permuted intermediate state, [k][b]
__device__ float g_s2_im[DIM * BSZ];
__device__ int   g_invperm[DIM];
__device__ float g_norm[BSZ];

// ---------------------------------------------------------------------------
__global__ void perm_kernel() {
    int j = blockIdx.x * blockDim.x + threadIdx.x;
    if (j >= DIM) return;
    int idx = j;
#pragma unroll
    for (int i = NW - 1; i >= 0; --i) {
        int c = i;
        int t = (i + 1) % NW;
        int cbit = (idx >> (NW - 1 - c)) & 1;
        idx ^= cbit << (NW - 1 - t);
    }
    g_invperm[idx] = j;     // idx == perm[j]
}

// ---------------------------------------------------------------------------
__global__ void norm_kernel(const float* __restrict__ x) {
    int b = blockIdx.x;
    const float4* xr = (const float4*)(x + (size_t)b * DIM);
    float s = 0.f;
    for (int i = threadIdx.x; i < DIM / 4; i += blockDim.x) {
        float4 v = xr[i];
        s += v.x * v.x + v.y * v.y + v.z * v.z + v.w * v.w;
    }
    __shared__ float red[4];
#pragma unroll
    for (int o = 16; o > 0; o >>= 1) s += __shfl_down_sync(0xffffffffu, s, o);
    if ((threadIdx.x & 31) == 0) red[threadIdx.x >> 5] = s;
    __syncthreads();
    if (threadIdx.x == 0) {
        float tot = red[0] + red[1] + red[2] + red[3];
        g_norm[b] = sqrtf(tot);
    }
}

// ---------------------------------------------------------------------------
// GEMM1 (dual): S1_re/S1_im[i,b] = sum_j U_re/U_im[i,j] * x[b,j]
// Packed f32x2 along m. Scatter epilogue applies the CNOT-ring permutation.
// ---------------------------------------------------------------------------
__global__ __launch_bounds__(256, 2)
void gemm1_kernel(const float* __restrict__ Ure,
                  const float* __restrict__ Uim,
                  const float* __restrict__ X) {
    __shared__ __align__(16) float As_re[2][BK][BM];
    __shared__ __align__(16) float As_im[2][BK][BM];
    __shared__ __align__(16) float Bs[2][BK][BN];

    const int tid = threadIdx.x;
    const int m0 = blockIdx.y * BM;
    const int n0 = blockIdx.x * BN;
    const int tx = tid & 15;   // n direction
    const int ty = tid >> 4;   // m direction

    const int ar = tid >> 1;
    const int ac = (tid & 1) << 2;
    const int br = (tid >> 1) & 63;
    const int bc = (tid & 1) << 2;

    const float* pAre = Ure + (size_t)(m0 + ar) * DIM + ac;
    const float* pAim = Uim + (size_t)(m0 + ar) * DIM + ac;
    const float* pB   = X   + (size_t)(n0 + br) * DIM + bc;

    float4 ra, ri, rb;
    ra = *(const float4*)pAre;
    ri = *(const float4*)pAim;
    if (tid < 128) rb = *(const float4*)pB;

    As_re[0][ac + 0][ar] = ra.x; As_re[0][ac + 1][ar] = ra.y;
    As_re[0][ac + 2][ar] = ra.z; As_re[0][ac + 3][ar] = ra.w;
    As_im[0][ac + 0][ar] = ri.x; As_im[0][ac + 1][ar] = ri.y;
    As_im[0][ac + 2][ar] = ri.z; As_im[0][ac + 3][ar] = ri.w;
    if (tid < 128) {
        Bs[0][bc + 0][br] = rb.x; Bs[0][bc + 1][br] = rb.y;
        Bs[0][bc + 2][br] = rb.z; Bs[0][bc + 3][br] = rb.w;
    }
    __syncthreads();

    // packed accumulators: [i2][j], i2 = m-pair index
    u64 c2r[4][4], c2i[4][4];
#pragma unroll
    for (int q = 0; q < 4; ++q)
#pragma unroll
        for (int j = 0; j < 4; ++j) { c2r[q][j] = 0ull; c2i[q][j] = 0ull; }

    for (int t = 0; t < NT; ++t) {
        const int cur = t & 1;
        if (t + 1 < NT) {
            const int ko = (t + 1) * BK;
            ra = *(const float4*)(pAre + ko);
            ri = *(const float4*)(pAim + ko);
            if (tid < 128) rb = *(const float4*)(pB + ko);
        }
#pragma unroll
        for (int k = 0; k < BK; ++k) {
            u64 a2r[4], a2i[4];
#pragma unroll
            for (int q = 0; q < 4; ++q) {
                a2r[q] = *(const u64*)&As_re[cur][k][ty * 8 + 2 * q];
                a2i[q] = *(const u64*)&As_im[cur][k][ty * 8 + 2 * q];
            }
            float4 b4 = *(const float4*)&Bs[cur][k][tx * 4];
            const float bs[4] = {b4.x, b4.y, b4.z, b4.w};
#pragma unroll
            for (int j = 0; j < 4; ++j) {
                u64 bd = dup2(bs[j]);
#pragma unroll
                for (int q = 0; q < 4; ++q) {
                    ffma2(c2r[q][j], a2r[q], bd);
                    ffma2(c2i[q][j], a2i[q], bd);
                }
            }
        }
        if (t + 1 < NT) {
            const int nb = cur ^ 1;
            As_re[nb][ac + 0][ar] = ra.x; As_re[nb][ac + 1][ar] = ra.y;
            As_re[nb][ac + 2][ar] = ra.z; As_re[nb][ac + 3][ar] = ra.w;
            As_im[nb][ac + 0][ar] = ri.x; As_im[nb][ac + 1][ar] = ri.y;
            As_im[nb][ac + 2][ar] = ri.z; As_im[nb][ac + 3][ar] = ri.w;
            if (tid < 128) {
                Bs[nb][bc + 0][br] = rb.x; Bs[nb][bc + 1][br] = rb.y;
                Bs[nb][bc + 2][br] = rb.z; Bs[nb][bc + 3][br] = rb.w;
            }
        }
        __syncthreads();
    }

#pragma unroll
    for (int q = 0; q < 4; ++q) {
        float r0[4], r1[4], i0[4], i1[4];
#pragma unroll
        for (int j = 0; j < 4; ++j) {
            unpack2(c2r[q][j], r0[j], r1[j]);
            unpack2(c2i[q][j], i0[j], i1[j]);
        }
        const int gm0 = m0 + ty * 8 + 2 * q;
        const int row0 = g_invperm[gm0];
        const int row1 = g_invperm[gm0 + 1];
        *(float4*)&g_s2_re[(size_t)row0 * BSZ + n0 + tx * 4] = make_float4(r0[0], r0[1], r0[2], r0[3]);
        *(float4*)&g_s2_im[(size_t)row0 * BSZ + n0 + tx * 4] = make_float4(i0[0], i0[1], i0[2], i0[3]);
        *(float4*)&g_s2_re[(size_t)row1 * BSZ + n0 + tx * 4] = make_float4(r1[0], r1[1], r1[2], r1[3]);
        *(float4*)&g_s2_im[(size_t)row1 * BSZ + n0 + tx * 4] = make_float4(i1[0], i1[1], i1[2], i1[3]);
    }
}

// ---------------------------------------------------------------------------
// GEMM2 (complex): out[b,i] = |sum_k (U1_re + i U1_im)[i,k] * s2[k,b]| / norm[b]
// Packed f32x2 along m.
// ---------------------------------------------------------------------------
__global__ __launch_bounds__(256, 2)
void gemm2_kernel(const float* __restrict__ U1re,
                  const float* __restrict__ U1im,
                  float* __restrict__ out) {
    __shared__ __align__(16) float As_re[2][BK][BM];
    __shared__ __align__(16) float As_im[2][BK][BM];
    __shared__ __align__(16) float Bs_re[2][BK][BN];
    __shared__ __align__(16) float Bs_im[2][BK][BN];

    const int tid = threadIdx.x;
    const int m0 = blockIdx.y * BM;
    const int n0 = blockIdx.x * BN;
    const int tx = tid & 15;
    const int ty = tid >> 4;

    const int ar = tid >> 1;
    const int ac = (tid & 1) << 2;

    const int t2 = tid & 127;
    const int bk = t2 >> 4;
    const int bn = (t2 & 15) << 2;

    const float* pAre = U1re + (size_t)(m0 + ar) * DIM + ac;
    const float* pAim = U1im + (size_t)(m0 + ar) * DIM + ac;
    const float* pB = (tid < 128 ? g_s2_re : g_s2_im) + (size_t)bk * BSZ + n0 + bn;

    float4 ra, ri, rb;
    ra = *(const float4*)pAre;
    ri = *(const float4*)pAim;
    rb = *(const float4*)pB;

    As_re[0][ac + 0][ar] = ra.x; As_re[0][ac + 1][ar] = ra.y;
    As_re[0][ac + 2][ar] = ra.z; As_re[0][ac + 3][ar] = ra.w;
    As_im[0][ac + 0][ar] = ri.x; As_im[0][ac + 1][ar] = ri.y;
    As_im[0][ac + 2][ar] = ri.z; As_im[0][ac + 3][ar] = ri.w;
    if (tid < 128) *(float4*)&Bs_re[0][bk][bn] = rb;
    else           *(float4*)&Bs_im[0][bk][bn] = rb;
    __syncthreads();

    u64 c2r[4][4], c2i[4][4];
#pragma unroll
    for (int q = 0; q < 4; ++q)
#pragma unroll
        for (int j = 0; j < 4; ++j) { c2r[q][j] = 0ull; c2i[q][j] = 0ull; }

    for (int t = 0; t < NT; ++t) {
        const int cur = t & 1;
        if (t + 1 < NT) {
            const int ko = (t + 1) * BK;
            ra = *(const float4*)(pAre + ko);
            ri = *(const float4*)(pAim + ko);
            rb = *(const float4*)(pB + (size_t)ko * BSZ);
        }
#pragma unroll
        for (int k = 0; k < BK; ++k) {
            u64 a2r[4], a2i[4];
#pragma unroll
            for (int q = 0; q < 4; ++q) {
                a2r[q] = *(const u64*)&As_re[cur][k][ty * 8 + 2 * q];
                a2i[q] = *(const u64*)&As_im[cur][k][ty * 8 + 2 * q];
            }
            float4 br4 = *(const float4*)&Bs_re[cur][k][tx * 4];
            float4 bi4 = *(const float4*)&Bs_im[cur][k][tx * 4];
            const float brs[4] = {br4.x, br4.y, br4.z, br4.w};
            const float bis[4] = {bi4.x, bi4.y, bi4.z, bi4.w};
#pragma unroll
            for (int j = 0; j < 4; ++j) {
                u64 brd  = dup2(brs[j]);
                u64 bid  = dup2(bis[j]);
                u64 bidn = dup2(-bis[j]);
#pragma unroll
                for (int q = 0; q < 4; ++q) {
                    ffma2(c2r[q][j], a2r[q], brd);
                    ffma2(c2r[q][j], a2i[q], bidn);
                    ffma2(c2i[q][j], a2r[q], bid);
                    ffma2(c2i[q][j], a2i[q], brd);
                }
            }
        }
        if (t + 1 < NT) {
            const int nb = cur ^ 1;
            As_re[nb][ac + 0][ar] = ra.x; As_re[nb][ac + 1][ar] = ra.y;
            As_re[nb][ac + 2][ar] = ra.z; As_re[nb][ac + 3][ar] = ra.w;
            As_im[nb][ac + 0][ar] = ri.x; As_im[nb][ac + 1][ar] = ri.y;
            As_im[nb][ac + 2][ar] = ri.z; As_im[nb][ac + 3][ar] = ri.w;
            if (tid < 128) *(float4*)&Bs_re[nb][bk][bn] = rb;
            else           *(float4*)&Bs_im[nb][bk][bn] = rb;
        }
        __syncthreads();
    }

    // epilogue: abs + deferred normalization, transposed write out[b, i]
#pragma unroll
    for (int j = 0; j < 4; ++j) {
        const int n = n0 + tx * 4 + j;
        const float inv = 1.0f / g_norm[n];
        float o[8];
#pragma unroll
        for (int q = 0; q < 4; ++q) {
            float rl, rh, il, ih;
            unpack2(c2r[q][j], rl, rh);
            unpack2(c2i[q][j], il, ih);
            o[2 * q]     = sqrtf(rl * rl + il * il) * inv;
            o[2 * q + 1] = sqrtf(rh * rh + ih * ih) * inv;
        }
        float* po = out + (size_t)n * DIM + m0 + ty * 8;
        *(float4*)po       = make_float4(o[0], o[1], o[2], o[3]);
        *(float4*)(po + 4) = make_float4(o[4], o[5], o[6], o[7]);
    }
}

// ---------------------------------------------------------------------------
extern "C" void kernel_launch(void* const* d_in, const int* in_sizes, int n_in,
                              void* d_out, int out_size) {
    const float* x     = (const float*)d_in[0];
    const float* U_re  = (const float*)d_in[1];
    const float* U_im  = (const float*)d_in[2];
    const float* U1_re = (const float*)d_in[3];
    const float* U1_im = (const float*)d_in[4];
    float* out = (float*)d_out;

    perm_kernel<<<DIM / 256, 256>>>();
    norm_kernel<<<BSZ, 128>>>(x);

    dim3 grid(BSZ / BN, DIM / BM);   // (16, 32)
    gemm1_kernel<<<grid, 256>>>(U_re, U_im, x);
    gemm2_kernel<<<grid, 256>>>(U1_re, U1_im, out);
}

// round 5
// speedup vs baseline: 2.2405x; 2.2405x over previous
#include <cuda_runtime.h>
#include <cuda_bf16.h>
#include <math.h>
#include <stdint.h>

#define DIM 4096
#define BSZ 1024
#define NW  12
#define BK  32
#define NS  (DIM / BK)
#define LDT 40
#define TILE (128 * LDT * 2)   // bytes per 128x32 bf16 tile (padded)

// ---------------- device-global scratch ----------------
__device__ __align__(16) __nv_bfloat16 g_Ar_h[(size_t)DIM * DIM];
__device__ __align__(16) __nv_bfloat16 g_Ar_l[(size_t)DIM * DIM];
__device__ __align__(16) __nv_bfloat16 g_Ai_h[(size_t)DIM * DIM];
__device__ __align__(16) __nv_bfloat16 g_Ai_l[(size_t)DIM * DIM];
__device__ __align__(16) __nv_bfloat16 g_Br_h[(size_t)DIM * DIM];
__device__ __align__(16) __nv_bfloat16 g_Br_l[(size_t)DIM * DIM];
__device__ __align__(16) __nv_bfloat16 g_Bi_h[(size_t)DIM * DIM];
__device__ __align__(16) __nv_bfloat16 g_Bi_l[(size_t)DIM * DIM];
__device__ __align__(16) __nv_bfloat16 g_x_h[(size_t)BSZ * DIM];
__device__ __align__(16) __nv_bfloat16 g_x_l[(size_t)BSZ * DIM];
__device__ __align__(16) __nv_bfloat16 g_sr_h[(size_t)BSZ * DIM];
__device__ __align__(16) __nv_bfloat16 g_sr_l[(size_t)BSZ * DIM];
__device__ __align__(16) __nv_bfloat16 g_si_h[(size_t)BSZ * DIM];
__device__ __align__(16) __nv_bfloat16 g_si_l[(size_t)BSZ * DIM];
__device__ __align__(16) __nv_bfloat16 g_sn_h[(size_t)BSZ * DIM];   // -si
__device__ __align__(16) __nv_bfloat16 g_sn_l[(size_t)BSZ * DIM];
__device__ int   g_perm[DIM];
__device__ float g_norm[BSZ];

// ---------------- helpers ----------------
__device__ __forceinline__ void split_bf(float v, __nv_bfloat16& h, __nv_bfloat16& l) {
    h = __float2bfloat16(v);
    l = __float2bfloat16(v - __bfloat162float(h));
}
__device__ __forceinline__ uint32_t pk(__nv_bfloat16 a, __nv_bfloat16 b) {
    return (uint32_t)__bfloat16_as_ushort(a) | ((uint32_t)__bfloat16_as_ushort(b) << 16);
}
__device__ __forceinline__ void cp16(uint32_t dst, const void* src) {
    asm volatile("cp.async.cg.shared.global [%0], [%1], 16;" :: "r"(dst), "l"(src));
}
#define CP_COMMIT() asm volatile("cp.async.commit_group;" ::: "memory")
#define CP_WAIT1()  asm volatile("cp.async.wait_group 1;" ::: "memory")
#define CP_WAIT0()  asm volatile("cp.async.wait_group 0;" ::: "memory")

__device__ __forceinline__ void ldsm4(uint32_t r[4], uint32_t addr) {
    asm volatile("ldmatrix.sync.aligned.m8n8.x4.shared.b16 {%0,%1,%2,%3}, [%4];"
        : "=r"(r[0]), "=r"(r[1]), "=r"(r[2]), "=r"(r[3]) : "r"(addr));
}
__device__ __forceinline__ void ldsm2(uint32_t r[2], uint32_t addr) {
    asm volatile("ldmatrix.sync.aligned.m8n8.x2.shared.b16 {%0,%1}, [%2];"
        : "=r"(r[0]), "=r"(r[1]) : "r"(addr));
}
__device__ __forceinline__ void mma16816(float c[4], const uint32_t a[4], const uint32_t b[2]) {
    asm volatile("mma.sync.aligned.m16n8k16.row.col.f32.bf16.bf16.f32 "
        "{%0,%1,%2,%3},{%4,%5,%6,%7},{%8,%9},{%0,%1,%2,%3};"
        : "+f"(c[0]), "+f"(c[1]), "+f"(c[2]), "+f"(c[3])
        : "r"(a[0]), "r"(a[1]), "r"(a[2]), "r"(a[3]), "r"(b[0]), "r"(b[1]));
}
#define MMA_BLK(C, A, B) do {                         \
    _Pragma("unroll") for (int _mt = 0; _mt < 4; ++_mt) \
    _Pragma("unroll") for (int _nt = 0; _nt < 4; ++_nt) \
        mma16816(C[_mt][_nt], A[_mt], B[_nt]);          \
} while (0)

// async-copy one 128x32 bf16 tile (rows row0.., cols k0..k0+31) into padded smem
__device__ __forceinline__ void cpa(const __nv_bfloat16* __restrict__ src,
                                    int row0, int k0, uint32_t smt, int tid) {
#pragma unroll
    for (int it = 0; it < 2; ++it) {
        int c = tid + it * 256;
        int r = c >> 2, kk = (c & 3) << 3;
        cp16(smt + (r * LDT + kk) * 2,
             src + (size_t)(row0 + r) * DIM + k0 + kk);
    }
}

// ---------------- prep kernels ----------------
__global__ void perm_kernel() {
    int j = blockIdx.x * blockDim.x + threadIdx.x;
    if (j >= DIM) return;
    int idx = j;
#pragma unroll
    for (int i = NW - 1; i >= 0; --i) {
        int c = i, t = (i + 1) % NW;
        int cb = (idx >> (NW - 1 - c)) & 1;
        idx ^= cb << (NW - 1 - t);
    }
    g_perm[j] = idx;   // out_state[j] = in_state[perm[j]]
}

__global__ void norm_kernel(const float* __restrict__ x) {
    int b = blockIdx.x;
    const float4* xr = (const float4*)(x + (size_t)b * DIM);
    float s = 0.f;
    for (int i = threadIdx.x; i < DIM / 4; i += blockDim.x) {
        float4 v = xr[i];
        s += v.x * v.x + v.y * v.y + v.z * v.z + v.w * v.w;
    }
    __shared__ float red[4];
#pragma unroll
    for (int o = 16; o > 0; o >>= 1) s += __shfl_down_sync(0xffffffffu, s, o);
    if ((threadIdx.x & 31) == 0) red[threadIdx.x >> 5] = s;
    __syncthreads();
    if (threadIdx.x == 0) g_norm[b] = sqrtf(red[0] + red[1] + red[2] + red[3]);
}

__global__ void conv_u_kernel(const float* __restrict__ Ure,
                              const float* __restrict__ Uim, int use_perm) {
    int j = blockIdx.x;
    int src = use_perm ? g_perm[j] : j;
    const float2* pr = (const float2*)(Ure + (size_t)src * DIM);
    const float2* pi = (const float2*)(Uim + (size_t)src * DIM);
    uint32_t* drh = (uint32_t*)((use_perm ? g_Ar_h : g_Br_h) + (size_t)j * DIM);
    uint32_t* drl = (uint32_t*)((use_perm ? g_Ar_l : g_Br_l) + (size_t)j * DIM);
    uint32_t* dih = (uint32_t*)((use_perm ? g_Ai_h : g_Bi_h) + (size_t)j * DIM);
    uint32_t* dil = (uint32_t*)((use_perm ? g_Ai_l : g_Bi_l) + (size_t)j * DIM);
    for (int c = threadIdx.x; c < DIM / 2; c += blockDim.x) {
        float2 v = pr[c];
        __nv_bfloat16 h0, l0, h1, l1;
        split_bf(v.x, h0, l0); split_bf(v.y, h1, l1);
        drh[c] = pk(h0, h1); drl[c] = pk(l0, l1);
        float2 w = pi[c];
        split_bf(w.x, h0, l0); split_bf(w.y, h1, l1);
        dih[c] = pk(h0, h1); dil[c] = pk(l0, l1);
    }
}

__global__ void conv_x_kernel(const float* __restrict__ x) {
    int b = blockIdx.x;
    const float2* px = (const float2*)(x + (size_t)b * DIM);
    uint32_t* dh = (uint32_t*)(g_x_h + (size_t)b * DIM);
    uint32_t* dl = (uint32_t*)(g_x_l + (size_t)b * DIM);
    for (int c = threadIdx.x; c < DIM / 2; c += blockDim.x) {
        float2 v = px[c];
        __nv_bfloat16 h0, l0, h1, l1;
        split_bf(v.x, h0, l0); split_bf(v.y, h1, l1);
        dh[c] = pk(h0, h1); dl[c] = pk(l0, l1);
    }
}

// ---------------------------------------------------------------------------
// GEMM1: s[j,b] = Uperm_re[j,:]·x[b,:] (+i Uperm_im·x). Split-bf16 3-term.
// Output: state split to [b][k] bf16 (sr, si, and sn = -si).
// ---------------------------------------------------------------------------
__global__ __launch_bounds__(256, 1) void gemm1_kernel() {
    extern __shared__ char smem[];
    uint32_t sbase = (uint32_t)__cvta_generic_to_shared(smem);
    const int tid = threadIdx.x, lane = tid & 31, wid = tid >> 5;
    const int g = lane >> 2, tg = lane & 3;
    const int wm0 = (wid >> 2) * 64, wn0 = (wid & 3) * 32;
    const int m0 = blockIdx.y * 128, n0 = blockIdx.x * 128;

    float cr[4][4][4], ci[4][4][4];
#pragma unroll
    for (int a = 0; a < 4; ++a)
#pragma unroll
        for (int b = 0; b < 4; ++b)
#pragma unroll
            for (int c = 0; c < 4; ++c) { cr[a][b][c] = 0.f; ci[a][b][c] = 0.f; }

#define G1_LOAD(st, t) do {                                   \
    uint32_t _sb = sbase + (st) * 6 * TILE; int _k0 = (t) * BK; \
    cpa(g_Ar_h, m0, _k0, _sb + 0 * TILE, tid);                 \
    cpa(g_Ar_l, m0, _k0, _sb + 1 * TILE, tid);                 \
    cpa(g_Ai_h, m0, _k0, _sb + 2 * TILE, tid);                 \
    cpa(g_Ai_l, m0, _k0, _sb + 3 * TILE, tid);                 \
    cpa(g_x_h,  n0, _k0, _sb + 4 * TILE, tid);                 \
    cpa(g_x_l,  n0, _k0, _sb + 5 * TILE, tid);                 \
} while (0)

    G1_LOAD(0, 0); CP_COMMIT();
    for (int t = 0; t < NS; ++t) {
        if (t + 1 < NS) { G1_LOAD((t + 1) & 1, t + 1); CP_COMMIT(); CP_WAIT1(); }
        else CP_WAIT0();
        __syncthreads();
        uint32_t sb = sbase + (t & 1) * 6 * TILE;
        const uint32_t boff = ((wn0 + (lane & 7)) * LDT + ((lane >> 3) & 1) * 8) * 2;
        const uint32_t aoff = ((wm0 + (lane & 15)) * LDT + (lane >> 4) * 8) * 2;
#pragma unroll
        for (int kk = 0; kk < 2; ++kk) {
            const uint32_t ko = kk * 32;   // 16 elems * 2B
            uint32_t bh[4][2], bl[4][2];
#pragma unroll
            for (int nt = 0; nt < 4; ++nt) {
                uint32_t o = boff + ko + nt * (8 * LDT * 2);
                ldsm2(bh[nt], sb + 4 * TILE + o);
                ldsm2(bl[nt], sb + 5 * TILE + o);
            }
            uint32_t ar[4][4], ai[4][4];
#pragma unroll
            for (int mt = 0; mt < 4; ++mt) {
                uint32_t o = aoff + ko + mt * (16 * LDT * 2);
                ldsm4(ar[mt], sb + 0 * TILE + o);
                ldsm4(ai[mt], sb + 2 * TILE + o);
            }
            MMA_BLK(cr, ar, bh);
            MMA_BLK(ci, ai, bh);
            MMA_BLK(cr, ar, bl);
            MMA_BLK(ci, ai, bl);
#pragma unroll
            for (int mt = 0; mt < 4; ++mt) {
                uint32_t o = aoff + ko + mt * (16 * LDT * 2);
                ldsm4(ar[mt], sb + 1 * TILE + o);
                ldsm4(ai[mt], sb + 3 * TILE + o);
            }
            MMA_BLK(cr, ar, bh);
            MMA_BLK(ci, ai, bh);
        }
        __syncthreads();
    }
#undef G1_LOAD

#pragma unroll
    for (int mt = 0; mt < 4; ++mt)
#pragma unroll
        for (int nt = 0; nt < 4; ++nt)
#pragma unroll
            for (int c = 0; c < 4; ++c) {
                const int m = m0 + wm0 + mt * 16 + g + ((c >> 1) << 3);
                const int b = n0 + wn0 + nt * 8 + tg * 2 + (c & 1);
                const size_t o = (size_t)b * DIM + m;
                __nv_bfloat16 h, l;
                split_bf(cr[mt][nt][c], h, l);
                g_sr_h[o] = h; g_sr_l[o] = l;
                split_bf(ci[mt][nt][c], h, l);
                g_si_h[o] = h; g_si_l[o] = l;
                g_sn_h[o] = __hneg(h); g_sn_l[o] = __hneg(l);
            }
}

// ---------------------------------------------------------------------------
// GEMM2: out[b,i] = | (U1_re + i U1_im)[i,:] · (sr + i si)[b,:] | / norm[b]
// re += Ar·Sr + Ai·Sn ; im += Ar·Si + Ai·Sr   (Sn = -Si), 3-term split each.
// ---------------------------------------------------------------------------
__global__ __launch_bounds__(256, 1) void gemm2_kernel(float* __restrict__ out) {
    extern __shared__ char smem[];
    uint32_t sbase = (uint32_t)__cvta_generic_to_shared(smem);
    const int tid = threadIdx.x, lane = tid & 31, wid = tid >> 5;
    const int g = lane >> 2, tg = lane & 3;
    const int wm0 = (wid >> 2) * 64, wn0 = (wid & 3) * 32;
    const int m0 = blockIdx.y * 128, n0 = blockIdx.x * 128;

    float cr[4][4][4], ci[4][4][4];
#pragma unroll
    for (int a = 0; a < 4; ++a)
#pragma unroll
        for (int b = 0; b < 4; ++b)
#pragma unroll
            for (int c = 0; c < 4; ++c) { cr[a][b][c] = 0.f; ci[a][b][c] = 0.f; }

    // stage arrays: 0 Brh 1 Brl 2 Bih 3 Bil | 4 Srh 5 Srl 6 Sih 7 Sil 8 Snh 9 Snl
#define G2_LOAD(st, t) do {                                    \
    uint32_t _sb = sbase + (st) * 10 * TILE; int _k0 = (t) * BK; \
    cpa(g_Br_h, m0, _k0, _sb + 0 * TILE, tid);                  \
    cpa(g_Br_l, m0, _k0, _sb + 1 * TILE, tid);                  \
    cpa(g_Bi_h, m0, _k0, _sb + 2 * TILE, tid);                  \
    cpa(g_Bi_l, m0, _k0, _sb + 3 * TILE, tid);                  \
    cpa(g_sr_h, n0, _k0, _sb + 4 * TILE, tid);                  \
    cpa(g_sr_l, n0, _k0, _sb + 5 * TILE, tid);                  \
    cpa(g_si_h, n0, _k0, _sb + 6 * TILE, tid);                  \
    cpa(g_si_l, n0, _k0, _sb + 7 * TILE, tid);                  \
    cpa(g_sn_h, n0, _k0, _sb + 8 * TILE, tid);                  \
    cpa(g_sn_l, n0, _k0, _sb + 9 * TILE, tid);                  \
} while (0)

    G2_LOAD(0, 0); CP_COMMIT();
    for (int t = 0; t < NS; ++t) {
        if (t + 1 < NS) { G2_LOAD((t + 1) & 1, t + 1); CP_COMMIT(); CP_WAIT1(); }
        else CP_WAIT0();
        __syncthreads();
        uint32_t sb = sbase + (t & 1) * 10 * TILE;
        const uint32_t boff = ((wn0 + (lane & 7)) * LDT + ((lane >> 3) & 1) * 8) * 2;
        const uint32_t aoff = ((wm0 + (lane & 15)) * LDT + (lane >> 4) * 8) * 2;
#pragma unroll
        for (int kk = 0; kk < 2; ++kk) {
            const uint32_t ko = kk * 32;
            uint32_t bsr[4][2], bsi[4][2], bsn[4][2];
            uint32_t ar[4][4], ai[4][4];
#pragma unroll
            for (int nt = 0; nt < 4; ++nt) {
                uint32_t o = boff + ko + nt * (8 * LDT * 2);
                ldsm2(bsr[nt], sb + 4 * TILE + o);
                ldsm2(bsi[nt], sb + 6 * TILE + o);
                ldsm2(bsn[nt], sb + 8 * TILE + o);
            }
#pragma unroll
            for (int mt = 0; mt < 4; ++mt) {
                uint32_t o = aoff + ko + mt * (16 * LDT * 2);
                ldsm4(ar[mt], sb + 0 * TILE + o);
                ldsm4(ai[mt], sb + 2 * TILE + o);
            }
            // (hi, hi)
            MMA_BLK(cr, ar, bsr); MMA_BLK(cr, ai, bsn);
            MMA_BLK(ci, ar, bsi); MMA_BLK(ci, ai, bsr);
            // (hi, lo)
#pragma unroll
            for (int nt = 0; nt < 4; ++nt) {
                uint32_t o = boff + ko + nt * (8 * LDT * 2);
                ldsm2(bsr[nt], sb + 5 * TILE + o);
                ldsm2(bsi[nt], sb + 7 * TILE + o);
                ldsm2(bsn[nt], sb + 9 * TILE + o);
            }
            MMA_BLK(cr, ar, bsr); MMA_BLK(cr, ai, bsn);
            MMA_BLK(ci, ar, bsi); MMA_BLK(ci, ai, bsr);
            // (lo, hi)
#pragma unroll
            for (int nt = 0; nt < 4; ++nt) {
                uint32_t o = boff + ko + nt * (8 * LDT * 2);
                ldsm2(bsr[nt], sb + 4 * TILE + o);
                ldsm2(bsi[nt], sb + 6 * TILE + o);
                ldsm2(bsn[nt], sb + 8 * TILE + o);
            }
#pragma unroll
            for (int mt = 0; mt < 4; ++mt) {
                uint32_t o = aoff + ko + mt * (16 * LDT * 2);
                ldsm4(ar[mt], sb + 1 * TILE + o);
                ldsm4(ai[mt], sb + 3 * TILE + o);
            }
            MMA_BLK(cr, ar, bsr); MMA_BLK(cr, ai, bsn);
            MMA_BLK(ci, ar, bsi); MMA_BLK(ci, ai, bsr);
        }
        __syncthreads();
    }
#undef G2_LOAD

#pragma unroll
    for (int mt = 0; mt < 4; ++mt)
#pragma unroll
        for (int nt = 0; nt < 4; ++nt)
#pragma unroll
            for (int c = 0; c < 4; ++c) {
                const int i = m0 + wm0 + mt * 16 + g + ((c >> 1) << 3);
                const int b = n0 + wn0 + nt * 8 + tg * 2 + (c & 1);
                const float re = cr[mt][nt][c], im = ci[mt][nt][c];
                out[(size_t)b * DIM + i] = sqrtf(re * re + im * im) / g_norm[b];
            }
}

// ---------------------------------------------------------------------------
extern "C" void kernel_launch(void* const* d_in, const int* in_sizes, int n_in,
                              void* d_out, int out_size) {
    const float* x     = (const float*)d_in[0];
    const float* U_re  = (const float*)d_in[1];
    const float* U_im  = (const float*)d_in[2];
    const float* U1_re = (const float*)d_in[3];
    const float* U1_im = (const float*)d_in[4];
    float* out = (float*)d_out;

    static int attr_done = 0;
    if (!attr_done) {
        cudaFuncSetAttribute(gemm1_kernel, cudaFuncAttributeMaxDynamicSharedMemorySize, 2 * 6 * TILE);
        cudaFuncSetAttribute(gemm2_kernel, cudaFuncAttributeMaxDynamicSharedMemorySize, 2 * 10 * TILE);
        attr_done = 1;
    }

    perm_kernel<<<DIM / 256, 256>>>();
    norm_kernel<<<BSZ, 128>>>(x);
    conv_u_kernel<<<DIM, 256>>>(U_re, U_im, 1);
    conv_u_kernel<<<DIM, 256>>>(U1_re, U1_im, 0);
    conv_x_kernel<<<BSZ, 256>>>(x);

    dim3 grid(BSZ / 128, DIM / 128);   // (8, 32)
    gemm1_kernel<<<grid, 256, 2 * 6 * TILE>>>();
    gemm2_kernel<<<grid, 256, 2 * 10 * TILE>>>(out);
}